// round 16
// baseline (speedup 1.0000x reference)
#include <cuda_runtime.h>
#include <cstdint>
#include <cstdio>

#define TT 2048
#define DD 2048
#define HDIM 1024
#define KTAG 22
#define ENDT 20
#define STARTT 21
#define NEGV -10000.0f
#define CPD 64            /* CTAs per direction (uniform 16 units each) */
#define NBLK (2 * CPD)
#define NGRP 8            /* counter shards per step == h slices */
#define GSTRIDE 64        /* u32 stride between shard counters (256B) */

typedef unsigned long long ull;

// ---- packed fp32x2 helpers (sm_103a dual-FMA) ----
__device__ __forceinline__ void pk2(ull& d, float x, float y) {
    asm("mov.b64 %0, {%1, %2};" : "=l"(d) : "r"(__float_as_uint(x)), "r"(__float_as_uint(y)));
}
__device__ __forceinline__ void upk2(float& x, float& y, ull d) {
    unsigned lo, hi;
    asm("mov.b64 {%0, %1}, %2;" : "=r"(lo), "=r"(hi) : "l"(d));
    x = __uint_as_float(lo); y = __uint_as_float(hi);
}
__device__ __forceinline__ void fma2(ull& d, ull a, ull b, ull c) {
    asm("fma.rn.f32x2 %0, %1, %2, %3;" : "=l"(d) : "l"(a), "l"(b), "l"(c));
}
__device__ __forceinline__ float4 ldcg4f(const float* p) {
    float4 v;
    asm volatile("ld.global.cg.v4.f32 {%0,%1,%2,%3}, [%4];"
                 : "=f"(v.x), "=f"(v.y), "=f"(v.z), "=f"(v.w) : "l"(p));
    return v;
}
__device__ __forceinline__ void red_release_add(unsigned* p, unsigned v) {
    asm volatile("red.release.gpu.global.add.u32 [%0], %1;" :: "l"(p), "r"(v) : "memory");
}
__device__ __forceinline__ unsigned ld_acquire(const unsigned* p) {
    unsigned v;
    asm volatile("ld.acquire.gpu.global.u32 %0, [%1];" : "=r"(v) : "l"(p) : "memory");
    return v;
}
// ---- fast activations (MUFU-based; validated rel_err-pass) ----
__device__ __forceinline__ float fsigmoid(float x) {
    float e, r;
    asm("ex2.approx.f32 %0, %1;" : "=f"(e) : "f"(-x * 1.4426950408889634f));
    asm("rcp.approx.f32 %0, %1;" : "=f"(r) : "f"(1.0f + e));
    return r;
}
__device__ __forceinline__ float ftanhf(float x) {
    x = fminf(fmaxf(x, -15.0f), 15.0f);
    float e, r;
    asm("ex2.approx.f32 %0, %1;" : "=f"(e) : "f"(x * 2.8853900817779268f));
    asm("rcp.approx.f32 %0, %1;" : "=f"(r) : "f"(e + 1.0f));
    return (e - 1.0f) * r;
}

// ---------------- scratch (device globals: allocation-free) ----------------
__device__ float g_G[2u * TT * 4096u];        // input gates, permuted [dir][t][unit*4+gate]
__device__ float g_lstm[(size_t)TT * 2048u];  // [t][fwd 1024 | rev 1024]
__device__ float g_feats[TT * KTAG];
__device__ unsigned g_cnt[2u * TT * NGRP * GSTRIDE];  // sharded per-step counters

// ---------------- init: zero counters (split in two launches: shifts recur
// into ncu's captured slot, -s 5 -c 1) ----------------
__global__ void init_kernel_a() {
    int n = TT * NGRP * GSTRIDE;                    // first half (dir 0)
    for (int i = blockIdx.x * blockDim.x + threadIdx.x; i < n; i += gridDim.x * blockDim.x)
        g_cnt[i] = 0u;
}
__global__ void init_kernel_b() {
    int n = TT * NGRP * GSTRIDE;                    // second half (dir 1)
    for (int i = blockIdx.x * blockDim.x + threadIdx.x; i < n; i += gridDim.x * blockDim.x)
        g_cnt[TT * NGRP * GSTRIDE + i] = 0u;
}

// ---------------- SGEMM: G = X @ W^T + bias (both dirs, permuted cols) ----------------
#define BM 128
#define BN 128
#define BKK 8
#define PADG 136

__global__ void __launch_bounds__(256) gemm_kernel(
    const float* __restrict__ X,
    const float* __restrict__ Wf, const float* __restrict__ Wr,
    const float* __restrict__ bihf, const float* __restrict__ bhhf,
    const float* __restrict__ bihr, const float* __restrict__ bhhr)
{
    __shared__ __align__(16) float As[2][BKK][PADG];
    __shared__ __align__(16) float Bs[2][BKK][PADG];

    int tid = threadIdx.x;
    int m0 = blockIdx.y * BM;
    int n0 = blockIdx.x * BN;
    int dir = n0 >> 12;
    const float* Wd  = dir ? Wr   : Wf;
    const float* bih = dir ? bihr : bihf;
    const float* bhh = dir ? bhhr : bhhf;

    int rid = tid >> 1;
    int kk  = (tid & 1) * 4;
    const float* aptr = X + (size_t)(m0 + rid) * DD + kk;
    int n  = n0 + rid;
    int wl = (n & 3) * HDIM + ((n & 4095) >> 2);
    const float* bptr = Wd + (size_t)wl * DD + kk;

    int tx = tid & 15, ty = tid >> 4;
    ull c2[8][4];
#pragma unroll
    for (int i = 0; i < 8; i++)
#pragma unroll
        for (int j = 0; j < 4; j++) c2[i][j] = 0ull;

    float4 a  = *(const float4*)aptr;
    float4 bv = *(const float4*)bptr;
#pragma unroll
    for (int j = 0; j < 4; j++) {
        As[0][kk + j][rid] = ((const float*)&a)[j];
        Bs[0][kk + j][rid] = ((const float*)&bv)[j];
    }
    __syncthreads();

    const int nk = DD / BKK;
    for (int kb = 0; kb < nk; kb++) {
        int p = kb & 1;
        if (kb + 1 < nk) {
            a  = *(const float4*)(aptr + (size_t)(kb + 1) * BKK);
            bv = *(const float4*)(bptr + (size_t)(kb + 1) * BKK);
        }
#pragma unroll
        for (int k = 0; k < BKK; k++) {
            float4 a0 = *(const float4*)&As[p][k][ty * 8];
            float4 a1 = *(const float4*)&As[p][k][ty * 8 + 4];
            ulonglong2 bq0 = *(const ulonglong2*)&Bs[p][k][tx * 8];
            ulonglong2 bq1 = *(const ulonglong2*)&Bs[p][k][tx * 8 + 4];
            float av[8] = {a0.x, a0.y, a0.z, a0.w, a1.x, a1.y, a1.z, a1.w};
#pragma unroll
            for (int i = 0; i < 8; i++) {
                ull ad; pk2(ad, av[i], av[i]);
                fma2(c2[i][0], ad, bq0.x, c2[i][0]);
                fma2(c2[i][1], ad, bq0.y, c2[i][1]);
                fma2(c2[i][2], ad, bq1.x, c2[i][2]);
                fma2(c2[i][3], ad, bq1.y, c2[i][3]);
            }
        }
        if (kb + 1 < nk) {
            int q = 1 - p;
#pragma unroll
            for (int j = 0; j < 4; j++) {
                As[q][kk + j][rid] = ((const float*)&a)[j];
                Bs[q][kk + j][rid] = ((const float*)&bv)[j];
            }
        }
        __syncthreads();
    }

    float bb[8];
#pragma unroll
    for (int j = 0; j < 8; j++) {
        int nn  = n0 + tx * 8 + j;
        int wl2 = (nn & 3) * HDIM + ((nn & 4095) >> 2);
        bb[j] = __ldg(&bih[wl2]) + __ldg(&bhh[wl2]);
    }
    size_t dbase = (size_t)dir * TT * 4096u;
#pragma unroll
    for (int i = 0; i < 8; i++) {
        int m = m0 + ty * 8 + i;
        float cc[8];
#pragma unroll
        for (int j = 0; j < 4; j++) upk2(cc[2 * j], cc[2 * j + 1], c2[i][j]);
        float* orow = g_G + dbase + (size_t)m * 4096u + ((n0 & 4095) + tx * 8);
        float4 o0 = {cc[0] + bb[0], cc[1] + bb[1], cc[2] + bb[2], cc[3] + bb[3]};
        float4 o1 = {cc[4] + bb[4], cc[5] + bb[5], cc[6] + bb[6], cc[7] + bb[7]};
        *(float4*)orow       = o0;
        *(float4*)(orow + 4) = o1;
    }
}

// ---------------- persistent bidirectional LSTM recurrence (R14, proven) ----------------
__global__ void __launch_bounds__(256, 1) recur_kernel(
    const float* __restrict__ Whh_f, const float* __restrict__ Whh_r,
    const float* __restrict__ c0, const float* __restrict__ h0)
{
    __shared__ __align__(16) float hbuf[2][HDIM];
    extern __shared__ __align__(16) float wsm[];   // 8 units * 4 rows * 1024 floats

    int b   = blockIdx.x;
    int dir = (b >= CPD) ? 1 : 0;
    int lb  = dir ? b - CPD : b;
    int u0  = lb * 16;
    int tid = threadIdx.x, lane = tid & 31, w = tid >> 5;
    int half = lane >> 4;
    const float* Whh = dir ? Whh_r : Whh_f;

    // stage 8 smem units (u0+8..u0+15)
    for (int su = 0; su < 8; su++) {
        int u = u0 + 8 + su;
#pragma unroll
        for (int r = 0; r < 4; r++) {
            const float4* src = (const float4*)(Whh + (size_t)(r * HDIM + u) * HDIM);
            ((float4*)(wsm + (su * 4 + r) * HDIM))[tid] = __ldg(src + tid);
        }
    }

    // stage register unit uA = u0 + w (4 gate rows, packed pairs)
    int uA = u0 + w;
    ull wA[64];
#pragma unroll
    for (int r = 0; r < 4; r++) {
        const float* row = Whh + (size_t)(r * HDIM + uA) * HDIM;
#pragma unroll
        for (int j = 0; j < 8; j++) {
            float4 v = __ldg((const float4*)(row + lane * 4 + j * 128));
            pk2(wA[r * 16 + 2 * j],     v.x, v.y);
            pk2(wA[r * 16 + 2 * j + 1], v.z, v.w);
        }
    }
    int uB = u0 + 8 + w;
    const float* wB = wsm + (w * 4) * HDIM;
    int ug = half ? uB : uA;                    // unit this half-warp activates

    float c_st = __ldg(&c0[dir * HDIM + ug]);

    const float* Gdir = g_G + (size_t)dir * TT * 4096u;
    float gc0, gc1, gc2, gc3;
    {
        int t0 = dir ? (TT - 1) : 0;
        const float* gp = Gdir + (size_t)t0 * 4096u + 4 * ug;
        gc0 = __ldg(gp + 0); gc1 = __ldg(gp + 1);
        gc2 = __ldg(gp + 2); gc3 = __ldg(gp + 3);
    }
    unsigned* fbase = g_cnt + (size_t)dir * TT * NGRP * GSTRIDE;
    int mygrp = lb >> 3;                         // producer shard == slice index
    __syncthreads();

    for (int s = 0; s < TT; s++) {
        // --- per-warp wait: lane0 polls shard w (its slice's 8 producers) ---
        float4 hv;
        if (s == 0) {
            hv = __ldg((const float4*)(h0 + dir * HDIM + w * 128 + lane * 4));
        } else {
            const unsigned* cp = fbase + (size_t)(s - 1) * NGRP * GSTRIDE + w * GSTRIDE;
            if (lane == 0) {
                unsigned v;
                do { v = ld_acquire(cp); } while (v < 8u);
            }
            __syncwarp();
            int pt = dir ? (TT - s) : (s - 1);
            hv = ldcg4f(g_lstm + (size_t)pt * 2048u + dir * HDIM + w * 128 + lane * 4);
        }
        int par = s & 1;
        ((float4*)hbuf[par])[w * 32 + lane] = hv;
        __syncthreads();                                   // BAR A (hbuf complete)

        // --- load full h as pre-packed pairs (zero movs) ---
        ull hh[16];
#pragma unroll
        for (int j = 0; j < 8; j++) {
            ulonglong2 hq = *(const ulonglong2*)(hbuf[par] + lane * 4 + j * 128);
            hh[2 * j]     = hq.x;
            hh[2 * j + 1] = hq.y;
        }

        // prefetch next step's g (per-lane, broadcast addresses)
        float gn0, gn1, gn2, gn3;
        {
            int s1 = (s + 1 < TT) ? s + 1 : s;
            int t1 = dir ? (TT - 1 - s1) : s1;
            const float* gp = Gdir + (size_t)t1 * 4096u + 4 * ug;
            gn0 = __ldg(gp + 0); gn1 = __ldg(gp + 1);
            gn2 = __ldg(gp + 2); gn3 = __ldg(gp + 3);
        }

        // --- dots: 4 register rows (unit A) + 4 smem rows (unit B) ---
        float acc[8];
#pragma unroll
        for (int r = 0; r < 4; r++) {
            ull a = 0ull;
#pragma unroll
            for (int jj = 0; jj < 16; jj++) fma2(a, wA[r * 16 + jj], hh[jj], a);
            float lo, hi; upk2(lo, hi, a);
            acc[r] = lo + hi;
        }
#pragma unroll
        for (int r = 0; r < 4; r++) {
            const float* wr = wB + r * HDIM;
            ull a = 0ull;
#pragma unroll
            for (int j = 0; j < 8; j++) {
                ulonglong2 wq = *(const ulonglong2*)(wr + lane * 4 + j * 128);
                fma2(a, wq.x, hh[2 * j],     a);
                fma2(a, wq.y, hh[2 * j + 1], a);
            }
            float lo, hi; upk2(lo, hi, a);
            acc[4 + r] = lo + hi;
        }

        // --- butterfly reduce all 8 accs ---
#pragma unroll
        for (int off = 16; off; off >>= 1) {
#pragma unroll
            for (int r = 0; r < 8; r++)
                acc[r] += __shfl_xor_sync(0xffffffffu, acc[r], off);
        }

        // --- activation (half 0 = unit A, half 1 = unit B; fast MUFU) ---
        float gi = acc[half * 4 + 0] + gc0;
        float gf = acc[half * 4 + 1] + gc1;
        float gg = acc[half * 4 + 2] + gc2;
        float go = acc[half * 4 + 3] + gc3;
        float iv = fsigmoid(gi);
        float fv = fsigmoid(gf);
        float gt = ftanhf(gg);
        float ov = fsigmoid(go);
        float cc = fv * c_st + iv * gt;
        c_st = cc;
        float h = ov * ftanhf(cc);

        int trow = dir ? (TT - 1 - s) : s;
        float* orow = g_lstm + (size_t)trow * 2048u + dir * HDIM;
        if (lane == 0)        orow[uA] = h;
        else if (lane == 16)  orow[uB] = h;

        __syncthreads();                                   // BAR B (h stores done)
        if (tid == 0)
            red_release_add(fbase + (size_t)s * NGRP * GSTRIDE + mygrp * GSTRIDE, 1u);
        gc0 = gn0; gc1 = gn1; gc2 = gn2; gc3 = gn3;
    }
}

// ---------------- feats = lstm_out @ W_tag^T + b_tag (deterministic reduction) ----------------
__global__ void __launch_bounds__(256) feats_kernel(
    const float* __restrict__ Wt, const float* __restrict__ bt)
{
    int t = blockIdx.x, tid = threadIdx.x;
    int lane = tid & 31, wid = tid >> 5;
    __shared__ float red2[KTAG][8];

    const float* row = g_lstm + (size_t)t * 2048u + tid * 8;
    float4 x0 = __ldg((const float4*)row);
    float4 x1 = __ldg((const float4*)(row + 4));

    for (int tag = 0; tag < KTAG; tag++) {
        const float* w = Wt + (size_t)tag * 2048u + tid * 8;
        float4 w0 = __ldg((const float4*)w);
        float4 w1 = __ldg((const float4*)(w + 4));
        float p = x0.x * w0.x + x0.y * w0.y + x0.z * w0.z + x0.w * w0.w
                + x1.x * w1.x + x1.y * w1.y + x1.z * w1.z + x1.w * w1.w;
#pragma unroll
        for (int off = 16; off; off >>= 1) p += __shfl_xor_sync(0xffffffffu, p, off);
        if (lane == 0) red2[tag][wid] = p;
    }
    __syncthreads();
    if (tid < KTAG) {
        float s = 0.f;
#pragma unroll
        for (int w2 = 0; w2 < 8; w2++) s += red2[tid][w2];
        g_feats[t * KTAG + tid] = s + __ldg(&bt[tid]);
    }
}

// ---------------- Viterbi DP + backtrack (single warp) ----------------
__global__ void viterbi_kernel(const float* __restrict__ trans, float* out, int out_size)
{
    extern __shared__ __align__(16) char vsm[];
    float* str  = (float*)vsm;
    float* fvs  = str + KTAG * KTAG;
    float* fbuf = fvs + KTAG;
    unsigned char* bp = (unsigned char*)(fbuf + 2 * 64 * KTAG);

    int lane = threadIdx.x;
    for (int i = lane; i < KTAG * KTAG; i += 32) str[i] = __ldg(&trans[i]);
    if (lane < KTAG) fvs[lane] = (lane == STARTT) ? 0.f : NEGV;
    for (int i = lane; i < 64 * KTAG; i += 32) fbuf[i] = __ldg(&g_feats[i]);
    __syncwarp();

    const int CH = 64, NC = TT / CH;
    for (int c2 = 0; c2 < NC; c2++) {
        float pf[44];
        if (c2 + 1 < NC) {
#pragma unroll
            for (int i = 0; i < 44; i++)
                pf[i] = __ldg(&g_feats[(c2 + 1) * CH * KTAG + lane + i * 32]);
        }
        float* cur = fbuf + (c2 & 1) * CH * KTAG;
        for (int tt2 = 0; tt2 < CH; tt2++) {
            int t = c2 * CH + tt2;
            float nf = 0.f;
            if (lane < KTAG) {
                float m = -3.4e38f; int bi = 0;
                const float* trow = str + lane * KTAG;
                for (int p2 = 0; p2 < KTAG; p2++) {
                    float v = trow[p2] + fvs[p2];
                    if (v > m) { m = v; bi = p2; }
                }
                nf = m + cur[tt2 * KTAG + lane];
                bp[t * KTAG + lane] = (unsigned char)bi;
            }
            __syncwarp();
            if (lane < KTAG) fvs[lane] = nf;
            __syncwarp();
        }
        if (c2 + 1 < NC) {
#pragma unroll
            for (int i = 0; i < 44; i++)
                fbuf[((c2 + 1) & 1) * CH * KTAG + lane + i * 32] = pf[i];
        }
        __syncwarp();
    }

    float tv = (lane < KTAG) ? fvs[lane] + str[ENDT * KTAG + lane] : -3.4e38f;
    int ti = lane;
#pragma unroll
    for (int off = 16; off; off >>= 1) {
        float ov = __shfl_down_sync(0xffffffffu, tv, off);
        int   oi = __shfl_down_sync(0xffffffffu, ti, off);
        if (ov > tv || (ov == tv && oi < ti)) { tv = ov; ti = oi; }
    }
    if (lane == 0) {
        float* po = out;
        int n_path = 0;
        if (out_size >= TT + 1)      { out[0] = tv; po = out + 1; n_path = TT; }
        else if (out_size == TT)     { po = out;    n_path = TT; }
        else if (out_size >= 1)      { out[0] = tv; po = out + 1; n_path = out_size - 1; }
        int cur2 = ti;
        for (int t = TT - 1; t >= 0; t--) {
            if (t < n_path) po[t] = (float)cur2;
            cur2 = bp[t * KTAG + cur2];
        }
    }
}

// ---------------- launcher ----------------
extern "C" void kernel_launch(void* const* d_in, const int* in_sizes, int n_in,
                              void* d_out, int out_size)
{
    const float* seq    = (const float*)d_in[0];
    const float* h0     = (const float*)d_in[1];
    const float* c0     = (const float*)d_in[2];
    const float* Wih_f  = (const float*)d_in[3];
    const float* Whh_f  = (const float*)d_in[4];
    const float* bih_f  = (const float*)d_in[5];
    const float* bhh_f  = (const float*)d_in[6];
    const float* Wih_r  = (const float*)d_in[7];
    const float* Whh_r  = (const float*)d_in[8];
    const float* bih_r  = (const float*)d_in[9];
    const float* bhh_r  = (const float*)d_in[10];
    const float* W_tag  = (const float*)d_in[11];
    const float* b_tag  = (const float*)d_in[12];
    const float* transp = (const float*)d_in[13];

    static int attr_done = 0;
    const int RECUR_SMEM = 8 * 4 * HDIM * 4;                        // 128 KB dynamic
    const int VIT_SMEM   = KTAG * KTAG * 4 + KTAG * 4 + 2 * 64 * KTAG * 4 + TT * KTAG;
    if (!attr_done) {
        cudaFuncSetAttribute(recur_kernel, cudaFuncAttributeMaxDynamicSharedMemorySize, RECUR_SMEM);
        cudaFuncSetAttribute(viterbi_kernel, cudaFuncAttributeMaxDynamicSharedMemorySize, VIT_SMEM);
        attr_done = 1;
    }

    // split init: shifts recur_kernel into ncu's capture slot (-s 5 -c 1)
    init_kernel_a<<<256, 512>>>();
    init_kernel_b<<<256, 512>>>();

    dim3 ggrid(8192 / BN, 2048 / BM);
    gemm_kernel<<<ggrid, 256>>>(seq, Wih_f, Wih_r, bih_f, bhh_f, bih_r, bhh_r);

    recur_kernel<<<NBLK, 256, RECUR_SMEM>>>(Whh_f, Whh_r, c0, h0);

    feats_kernel<<<TT, 256>>>(W_tag, b_tag);

    viterbi_kernel<<<1, 32, VIT_SMEM>>>(transp, (float*)d_out, out_size);
}

// round 17
// speedup vs baseline: 1.5148x; 1.5148x over previous
#include <cuda_runtime.h>
#include <cstdint>
#include <cstdio>

#define TT 2048
#define DD 2048
#define HDIM 1024
#define KTAG 22
#define ENDT 20
#define STARTT 21
#define NEGV -10000.0f
#define CPD 64            /* CTAs per direction (uniform 16 units each) */
#define NBLK (2 * CPD)
#define NGRP 8            /* counter shards per step == h slices */
#define GSTRIDE 64        /* u32 stride between shard counters (256B) */
#define WARPS_PER_SHARD 64u  /* 8 CTAs x 8 warps release per shard */

typedef unsigned long long ull;

// ---- packed fp32x2 helpers (sm_103a dual-FMA) ----
__device__ __forceinline__ void pk2(ull& d, float x, float y) {
    asm("mov.b64 %0, {%1, %2};" : "=l"(d) : "r"(__float_as_uint(x)), "r"(__float_as_uint(y)));
}
__device__ __forceinline__ void upk2(float& x, float& y, ull d) {
    unsigned lo, hi;
    asm("mov.b64 {%0, %1}, %2;" : "=r"(lo), "=r"(hi) : "l"(d));
    x = __uint_as_float(lo); y = __uint_as_float(hi);
}
__device__ __forceinline__ void fma2(ull& d, ull a, ull b, ull c) {
    asm("fma.rn.f32x2 %0, %1, %2, %3;" : "=l"(d) : "l"(a), "l"(b), "l"(c));
}
__device__ __forceinline__ float4 ldcg4f(const float* p) {
    float4 v;
    asm volatile("ld.global.cg.v4.f32 {%0,%1,%2,%3}, [%4];"
                 : "=f"(v.x), "=f"(v.y), "=f"(v.z), "=f"(v.w) : "l"(p));
    return v;
}
__device__ __forceinline__ void red_release_add(unsigned* p, unsigned v) {
    asm volatile("red.release.gpu.global.add.u32 [%0], %1;" :: "l"(p), "r"(v) : "memory");
}
__device__ __forceinline__ unsigned ld_acquire(const unsigned* p) {
    unsigned v;
    asm volatile("ld.acquire.gpu.global.u32 %0, [%1];" : "=r"(v) : "l"(p) : "memory");
    return v;
}
// ---- fast activations (MUFU-based; validated rel_err-pass) ----
__device__ __forceinline__ float fsigmoid(float x) {
    float e, r;
    asm("ex2.approx.f32 %0, %1;" : "=f"(e) : "f"(-x * 1.4426950408889634f));
    asm("rcp.approx.f32 %0, %1;" : "=f"(r) : "f"(1.0f + e));
    return r;
}
__device__ __forceinline__ float ftanhf(float x) {
    x = fminf(fmaxf(x, -15.0f), 15.0f);
    float e, r;
    asm("ex2.approx.f32 %0, %1;" : "=f"(e) : "f"(x * 2.8853900817779268f));
    asm("rcp.approx.f32 %0, %1;" : "=f"(r) : "f"(e + 1.0f));
    return (e - 1.0f) * r;
}

// ---------------- scratch (device globals: allocation-free) ----------------
__device__ float g_G[2u * TT * 4096u];        // input gates, permuted [dir][t][unit*4+gate]
__device__ float g_lstm[(size_t)TT * 2048u];  // [t][fwd 1024 | rev 1024]
__device__ float g_feats[TT * KTAG];
__device__ unsigned g_cnt[2u * TT * NGRP * GSTRIDE];  // sharded per-step counters

// ---------------- init: zero counters ----------------
__global__ void init_kernel() {
    int n = 2 * TT * NGRP * GSTRIDE;
    for (int i = blockIdx.x * blockDim.x + threadIdx.x; i < n; i += gridDim.x * blockDim.x)
        g_cnt[i] = 0u;
}

// ---------------- SGEMM: G = X @ W^T + bias (both dirs, permuted cols) ----------------
#define BM 128
#define BN 128
#define BKK 8
#define PADG 136

__global__ void __launch_bounds__(256) gemm_kernel(
    const float* __restrict__ X,
    const float* __restrict__ Wf, const float* __restrict__ Wr,
    const float* __restrict__ bihf, const float* __restrict__ bhhf,
    const float* __restrict__ bihr, const float* __restrict__ bhhr)
{
    __shared__ __align__(16) float As[2][BKK][PADG];
    __shared__ __align__(16) float Bs[2][BKK][PADG];

    int tid = threadIdx.x;
    int m0 = blockIdx.y * BM;
    int n0 = blockIdx.x * BN;
    int dir = n0 >> 12;
    const float* Wd  = dir ? Wr   : Wf;
    const float* bih = dir ? bihr : bihf;
    const float* bhh = dir ? bhhr : bhhf;

    int rid = tid >> 1;
    int kk  = (tid & 1) * 4;
    const float* aptr = X + (size_t)(m0 + rid) * DD + kk;
    int n  = n0 + rid;
    int wl = (n & 3) * HDIM + ((n & 4095) >> 2);
    const float* bptr = Wd + (size_t)wl * DD + kk;

    int tx = tid & 15, ty = tid >> 4;
    ull c2[8][4];
#pragma unroll
    for (int i = 0; i < 8; i++)
#pragma unroll
        for (int j = 0; j < 4; j++) c2[i][j] = 0ull;

    float4 a  = *(const float4*)aptr;
    float4 bv = *(const float4*)bptr;
#pragma unroll
    for (int j = 0; j < 4; j++) {
        As[0][kk + j][rid] = ((const float*)&a)[j];
        Bs[0][kk + j][rid] = ((const float*)&bv)[j];
    }
    __syncthreads();

    const int nk = DD / BKK;
    for (int kb = 0; kb < nk; kb++) {
        int p = kb & 1;
        if (kb + 1 < nk) {
            a  = *(const float4*)(aptr + (size_t)(kb + 1) * BKK);
            bv = *(const float4*)(bptr + (size_t)(kb + 1) * BKK);
        }
#pragma unroll
        for (int k = 0; k < BKK; k++) {
            float4 a0 = *(const float4*)&As[p][k][ty * 8];
            float4 a1 = *(const float4*)&As[p][k][ty * 8 + 4];
            ulonglong2 bq0 = *(const ulonglong2*)&Bs[p][k][tx * 8];
            ulonglong2 bq1 = *(const ulonglong2*)&Bs[p][k][tx * 8 + 4];
            float av[8] = {a0.x, a0.y, a0.z, a0.w, a1.x, a1.y, a1.z, a1.w};
#pragma unroll
            for (int i = 0; i < 8; i++) {
                ull ad; pk2(ad, av[i], av[i]);
                fma2(c2[i][0], ad, bq0.x, c2[i][0]);
                fma2(c2[i][1], ad, bq0.y, c2[i][1]);
                fma2(c2[i][2], ad, bq1.x, c2[i][2]);
                fma2(c2[i][3], ad, bq1.y, c2[i][3]);
            }
        }
        if (kb + 1 < nk) {
            int q = 1 - p;
#pragma unroll
            for (int j = 0; j < 4; j++) {
                As[q][kk + j][rid] = ((const float*)&a)[j];
                Bs[q][kk + j][rid] = ((const float*)&bv)[j];
            }
        }
        __syncthreads();
    }

    float bb[8];
#pragma unroll
    for (int j = 0; j < 8; j++) {
        int nn  = n0 + tx * 8 + j;
        int wl2 = (nn & 3) * HDIM + ((nn & 4095) >> 2);
        bb[j] = __ldg(&bih[wl2]) + __ldg(&bhh[wl2]);
    }
    size_t dbase = (size_t)dir * TT * 4096u;
#pragma unroll
    for (int i = 0; i < 8; i++) {
        int m = m0 + ty * 8 + i;
        float cc[8];
#pragma unroll
        for (int j = 0; j < 4; j++) upk2(cc[2 * j], cc[2 * j + 1], c2[i][j]);
        float* orow = g_G + dbase + (size_t)m * 4096u + ((n0 & 4095) + tx * 8);
        float4 o0 = {cc[0] + bb[0], cc[1] + bb[1], cc[2] + bb[2], cc[3] + bb[3]};
        float4 o1 = {cc[4] + bb[4], cc[5] + bb[5], cc[6] + bb[6], cc[7] + bb[7]};
        *(float4*)orow       = o0;
        *(float4*)(orow + 4) = o1;
    }
}

// ---------------- persistent bidirectional LSTM recurrence v17 ----------------
// R14 core; BAR B removed. Each warp releases its own +1 to its CTA's shard
// counter after __syncwarp (HB covers lane16's store). Shard target = 64
// warp-arrivals. Fast warps flow into the next step's poll/load, overlapping
// their ld.cg with slow warps' dots.
__global__ void __launch_bounds__(256, 1) recur_kernel(
    const float* __restrict__ Whh_f, const float* __restrict__ Whh_r,
    const float* __restrict__ c0, const float* __restrict__ h0)
{
    __shared__ __align__(16) float hbuf[2][HDIM];
    extern __shared__ __align__(16) float wsm[];   // 8 units * 4 rows * 1024 floats

    int b   = blockIdx.x;
    int dir = (b >= CPD) ? 1 : 0;
    int lb  = dir ? b - CPD : b;
    int u0  = lb * 16;
    int tid = threadIdx.x, lane = tid & 31, w = tid >> 5;
    int half = lane >> 4;
    const float* Whh = dir ? Whh_r : Whh_f;

    // stage 8 smem units (u0+8..u0+15)
    for (int su = 0; su < 8; su++) {
        int u = u0 + 8 + su;
#pragma unroll
        for (int r = 0; r < 4; r++) {
            const float4* src = (const float4*)(Whh + (size_t)(r * HDIM + u) * HDIM);
            ((float4*)(wsm + (su * 4 + r) * HDIM))[tid] = __ldg(src + tid);
        }
    }

    // stage register unit uA = u0 + w (4 gate rows, packed pairs)
    int uA = u0 + w;
    ull wA[64];
#pragma unroll
    for (int r = 0; r < 4; r++) {
        const float* row = Whh + (size_t)(r * HDIM + uA) * HDIM;
#pragma unroll
        for (int j = 0; j < 8; j++) {
            float4 v = __ldg((const float4*)(row + lane * 4 + j * 128));
            pk2(wA[r * 16 + 2 * j],     v.x, v.y);
            pk2(wA[r * 16 + 2 * j + 1], v.z, v.w);
        }
    }
    int uB = u0 + 8 + w;
    const float* wB = wsm + (w * 4) * HDIM;
    int ug = half ? uB : uA;                    // unit this half-warp activates

    float c_st = __ldg(&c0[dir * HDIM + ug]);

    const float* Gdir = g_G + (size_t)dir * TT * 4096u;
    float gc0, gc1, gc2, gc3;
    {
        int t0 = dir ? (TT - 1) : 0;
        const float* gp = Gdir + (size_t)t0 * 4096u + 4 * ug;
        gc0 = __ldg(gp + 0); gc1 = __ldg(gp + 1);
        gc2 = __ldg(gp + 2); gc3 = __ldg(gp + 3);
    }
    unsigned* fbase = g_cnt + (size_t)dir * TT * NGRP * GSTRIDE;
    int mygrp = lb >> 3;                         // this CTA's shard
    unsigned* myrel0 = fbase + mygrp * GSTRIDE;  // release target, step-indexed
    __syncthreads();

    for (int s = 0; s < TT; s++) {
        // --- per-warp wait: lane0 polls shard w (64 warp-arrivals) ---
        float4 hv;
        if (s == 0) {
            hv = __ldg((const float4*)(h0 + dir * HDIM + w * 128 + lane * 4));
        } else {
            const unsigned* cp = fbase + (size_t)(s - 1) * NGRP * GSTRIDE + w * GSTRIDE;
            if (lane == 0) {
                unsigned v;
                do { v = ld_acquire(cp); } while (v < WARPS_PER_SHARD);
            }
            __syncwarp();
            int pt = dir ? (TT - s) : (s - 1);
            hv = ldcg4f(g_lstm + (size_t)pt * 2048u + dir * HDIM + w * 128 + lane * 4);
        }
        int par = s & 1;
        ((float4*)hbuf[par])[w * 32 + lane] = hv;
        __syncthreads();                                   // BAR A (hbuf complete)

        // --- load full h as pre-packed pairs (zero movs) ---
        ull hh[16];
#pragma unroll
        for (int j = 0; j < 8; j++) {
            ulonglong2 hq = *(const ulonglong2*)(hbuf[par] + lane * 4 + j * 128);
            hh[2 * j]     = hq.x;
            hh[2 * j + 1] = hq.y;
        }

        // prefetch next step's g (per-lane, broadcast addresses)
        float gn0, gn1, gn2, gn3;
        {
            int s1 = (s + 1 < TT) ? s + 1 : s;
            int t1 = dir ? (TT - 1 - s1) : s1;
            const float* gp = Gdir + (size_t)t1 * 4096u + 4 * ug;
            gn0 = __ldg(gp + 0); gn1 = __ldg(gp + 1);
            gn2 = __ldg(gp + 2); gn3 = __ldg(gp + 3);
        }

        // --- dots: 4 register rows (unit A) + 4 smem rows (unit B) ---
        float acc[8];
#pragma unroll
        for (int r = 0; r < 4; r++) {
            ull a = 0ull;
#pragma unroll
            for (int jj = 0; jj < 16; jj++) fma2(a, wA[r * 16 + jj], hh[jj], a);
            float lo, hi; upk2(lo, hi, a);
            acc[r] = lo + hi;
        }
#pragma unroll
        for (int r = 0; r < 4; r++) {
            const float* wr = wB + r * HDIM;
            ull a = 0ull;
#pragma unroll
            for (int j = 0; j < 8; j++) {
                ulonglong2 wq = *(const ulonglong2*)(wr + lane * 4 + j * 128);
                fma2(a, wq.x, hh[2 * j],     a);
                fma2(a, wq.y, hh[2 * j + 1], a);
            }
            float lo, hi; upk2(lo, hi, a);
            acc[4 + r] = lo + hi;
        }

        // --- butterfly reduce all 8 accs ---
#pragma unroll
        for (int off = 16; off; off >>= 1) {
#pragma unroll
            for (int r = 0; r < 8; r++)
                acc[r] += __shfl_xor_sync(0xffffffffu, acc[r], off);
        }

        // --- activation (half 0 = unit A, half 1 = unit B; fast MUFU) ---
        float gi = acc[half * 4 + 0] + gc0;
        float gf = acc[half * 4 + 1] + gc1;
        float gg = acc[half * 4 + 2] + gc2;
        float go = acc[half * 4 + 3] + gc3;
        float iv = fsigmoid(gi);
        float fv = fsigmoid(gf);
        float gt = ftanhf(gg);
        float ov = fsigmoid(go);
        float cc = fv * c_st + iv * gt;
        c_st = cc;
        float h = ov * ftanhf(cc);

        int trow = dir ? (TT - 1 - s) : s;
        float* orow = g_lstm + (size_t)trow * 2048u + dir * HDIM;
        if (lane == 0)        orow[uA] = h;
        else if (lane == 16)  orow[uB] = h;

        // --- per-warp release: no CTA barrier. __syncwarp gives the HB edge
        // for lane16's store; red.release is cumulative. ---
        __syncwarp();
        if (lane == 0)
            red_release_add(myrel0 + (size_t)s * NGRP * GSTRIDE, 1u);
        gc0 = gn0; gc1 = gn1; gc2 = gn2; gc3 = gn3;
    }
}

// ---------------- feats = lstm_out @ W_tag^T + b_tag (deterministic reduction) ----------------
__global__ void __launch_bounds__(256) feats_kernel(
    const float* __restrict__ Wt, const float* __restrict__ bt)
{
    int t = blockIdx.x, tid = threadIdx.x;
    int lane = tid & 31, wid = tid >> 5;
    __shared__ float red2[KTAG][8];

    const float* row = g_lstm + (size_t)t * 2048u + tid * 8;
    float4 x0 = __ldg((const float4*)row);
    float4 x1 = __ldg((const float4*)(row + 4));

    for (int tag = 0; tag < KTAG; tag++) {
        const float* w = Wt + (size_t)tag * 2048u + tid * 8;
        float4 w0 = __ldg((const float4*)w);
        float4 w1 = __ldg((const float4*)(w + 4));
        float p = x0.x * w0.x + x0.y * w0.y + x0.z * w0.z + x0.w * w0.w
                + x1.x * w1.x + x1.y * w1.y + x1.z * w1.z + x1.w * w1.w;
#pragma unroll
        for (int off = 16; off; off >>= 1) p += __shfl_xor_sync(0xffffffffu, p, off);
        if (lane == 0) red2[tag][wid] = p;
    }
    __syncthreads();
    if (tid < KTAG) {
        float s = 0.f;
#pragma unroll
        for (int w2 = 0; w2 < 8; w2++) s += red2[tid][w2];
        g_feats[t * KTAG + tid] = s + __ldg(&bt[tid]);
    }
}

// ---------------- Viterbi DP + backtrack (single warp) ----------------
__global__ void viterbi_kernel(const float* __restrict__ trans, float* out, int out_size)
{
    extern __shared__ __align__(16) char vsm[];
    float* str  = (float*)vsm;
    float* fvs  = str + KTAG * KTAG;
    float* fbuf = fvs + KTAG;
    unsigned char* bp = (unsigned char*)(fbuf + 2 * 64 * KTAG);

    int lane = threadIdx.x;
    for (int i = lane; i < KTAG * KTAG; i += 32) str[i] = __ldg(&trans[i]);
    if (lane < KTAG) fvs[lane] = (lane == STARTT) ? 0.f : NEGV;
    for (int i = lane; i < 64 * KTAG; i += 32) fbuf[i] = __ldg(&g_feats[i]);
    __syncwarp();

    const int CH = 64, NC = TT / CH;
    for (int c2 = 0; c2 < NC; c2++) {
        float pf[44];
        if (c2 + 1 < NC) {
#pragma unroll
            for (int i = 0; i < 44; i++)
                pf[i] = __ldg(&g_feats[(c2 + 1) * CH * KTAG + lane + i * 32]);
        }
        float* cur = fbuf + (c2 & 1) * CH * KTAG;
        for (int tt2 = 0; tt2 < CH; tt2++) {
            int t = c2 * CH + tt2;
            float nf = 0.f;
            if (lane < KTAG) {
                float m = -3.4e38f; int bi = 0;
                const float* trow = str + lane * KTAG;
                for (int p2 = 0; p2 < KTAG; p2++) {
                    float v = trow[p2] + fvs[p2];
                    if (v > m) { m = v; bi = p2; }
                }
                nf = m + cur[tt2 * KTAG + lane];
                bp[t * KTAG + lane] = (unsigned char)bi;
            }
            __syncwarp();
            if (lane < KTAG) fvs[lane] = nf;
            __syncwarp();
        }
        if (c2 + 1 < NC) {
#pragma unroll
            for (int i = 0; i < 44; i++)
                fbuf[((c2 + 1) & 1) * CH * KTAG + lane + i * 32] = pf[i];
        }
        __syncwarp();
    }

    float tv = (lane < KTAG) ? fvs[lane] + str[ENDT * KTAG + lane] : -3.4e38f;
    int ti = lane;
#pragma unroll
    for (int off = 16; off; off >>= 1) {
        float ov = __shfl_down_sync(0xffffffffu, tv, off);
        int   oi = __shfl_down_sync(0xffffffffu, ti, off);
        if (ov > tv || (ov == tv && oi < ti)) { tv = ov; ti = oi; }
    }
    if (lane == 0) {
        float* po = out;
        int n_path = 0;
        if (out_size >= TT + 1)      { out[0] = tv; po = out + 1; n_path = TT; }
        else if (out_size == TT)     { po = out;    n_path = TT; }
        else if (out_size >= 1)      { out[0] = tv; po = out + 1; n_path = out_size - 1; }
        int cur2 = ti;
        for (int t = TT - 1; t >= 0; t--) {
            if (t < n_path) po[t] = (float)cur2;
            cur2 = bp[t * KTAG + cur2];
        }
    }
}

// ---------------- launcher ----------------
extern "C" void kernel_launch(void* const* d_in, const int* in_sizes, int n_in,
                              void* d_out, int out_size)
{
    const float* seq    = (const float*)d_in[0];
    const float* h0     = (const float*)d_in[1];
    const float* c0     = (const float*)d_in[2];
    const float* Wih_f  = (const float*)d_in[3];
    const float* Whh_f  = (const float*)d_in[4];
    const float* bih_f  = (const float*)d_in[5];
    const float* bhh_f  = (const float*)d_in[6];
    const float* Wih_r  = (const float*)d_in[7];
    const float* Whh_r  = (const float*)d_in[8];
    const float* bih_r  = (const float*)d_in[9];
    const float* bhh_r  = (const float*)d_in[10];
    const float* W_tag  = (const float*)d_in[11];
    const float* b_tag  = (const float*)d_in[12];
    const float* transp = (const float*)d_in[13];

    static int attr_done = 0;
    const int RECUR_SMEM = 8 * 4 * HDIM * 4;                        // 128 KB dynamic
    const int VIT_SMEM   = KTAG * KTAG * 4 + KTAG * 4 + 2 * 64 * KTAG * 4 + TT * KTAG;
    if (!attr_done) {
        cudaFuncSetAttribute(recur_kernel, cudaFuncAttributeMaxDynamicSharedMemorySize, RECUR_SMEM);
        cudaFuncSetAttribute(viterbi_kernel, cudaFuncAttributeMaxDynamicSharedMemorySize, VIT_SMEM);
        attr_done = 1;
    }

    init_kernel<<<512, 512>>>();

    dim3 ggrid(8192 / BN, 2048 / BM);
    gemm_kernel<<<ggrid, 256>>>(seq, Wih_f, Wih_r, bih_f, bhh_f, bih_r, bhh_r);

    recur_kernel<<<NBLK, 256, RECUR_SMEM>>>(Whh_f, Whh_r, c0, h0);

    feats_kernel<<<TT, 256>>>(W_tag, b_tag);

    viterbi_kernel<<<1, 32, VIT_SMEM>>>(transp, (float*)d_out, out_size);
}